// round 5
// baseline (speedup 1.0000x reference)
#include <cuda_runtime.h>
#include <math.h>

#define BATCH 8192
#define DIM 16
#define DIM1 48
#define VOCAB 32000
#define TTH 20

// Intermediate o = [BATCH, 16] between the two kernels (static scratch, no allocs).
__device__ float g_o[BATCH * DIM];

// ---------------------------------------------------------------------------
// helpers
// ---------------------------------------------------------------------------
template <int N>
__device__ __forceinline__ float dotN(const float* __restrict__ w,
                                      const float* __restrict__ x) {
    float acc = 0.f;
#pragma unroll
    for (int k = 0; k < N / 4; k++) {
        float4 wv = *reinterpret_cast<const float4*>(w + 4 * k);
        acc += wv.x * x[4 * k + 0];
        acc += wv.y * x[4 * k + 1];
        acc += wv.z * x[4 * k + 2];
        acc += wv.w * x[4 * k + 3];
    }
    return acc;
}

__device__ __forceinline__ void ln_silu(float* __restrict__ h,
                                        const float* __restrict__ g,
                                        const float* __restrict__ b) {
    float m = 0.f;
#pragma unroll
    for (int j = 0; j < DIM1; j++) m += h[j];
    m *= (1.f / DIM1);
    float v = 0.f;
#pragma unroll
    for (int j = 0; j < DIM1; j++) {
        float d = h[j] - m;
        v += d * d;
    }
    v *= (1.f / DIM1);
    float inv = rsqrtf(v + 1e-5f);
#pragma unroll
    for (int j = 0; j < DIM1; j++) {
        float t = (h[j] - m) * inv * __ldg(&g[j]) + __ldg(&b[j]);
        h[j] = t / (1.f + expf(-t));
    }
}

// ---------------------------------------------------------------------------
// Kernel A: per-row MLP pipeline -> g_o[row][16]
// One thread per row. WM1/WM2/WM3 staged in static shared (46 KB).
// ---------------------------------------------------------------------------
__global__ void __launch_bounds__(64) rowmlp_kernel(
    const float* __restrict__ we, const float* __restrict__ ctx,
    const float* __restrict__ th,
    const float* __restrict__ WI1, const float* __restrict__ bI1,
    const float* __restrict__ WA1, const float* __restrict__ bA1,
    const float* __restrict__ WM1, const float* __restrict__ bM1,
    const float* __restrict__ WM2, const float* __restrict__ bM2,
    const float* __restrict__ WM3, const float* __restrict__ bM3,
    const float* __restrict__ lng, const float* __restrict__ lnb,
    const float* __restrict__ WO1, const float* __restrict__ bO1) {
    __shared__ __align__(16) float sWM1[DIM1 * 80];
    __shared__ __align__(16) float sWM2[DIM1 * 112];
    __shared__ __align__(16) float sWM3[DIM1 * DIM1];

    for (int i = threadIdx.x; i < DIM1 * 80; i += blockDim.x) sWM1[i] = WM1[i];
    for (int i = threadIdx.x; i < DIM1 * 112; i += blockDim.x) sWM2[i] = WM2[i];
    for (int i = threadIdx.x; i < DIM1 * DIM1; i += blockDim.x) sWM3[i] = WM3[i];
    __syncthreads();

    int row = blockIdx.x * blockDim.x + threadIdx.x;
    if (row >= BATCH) return;

    float x[DIM], c[DIM];
    {
        const float4* wp = reinterpret_cast<const float4*>(we + (size_t)row * DIM);
        const float4* cp = reinterpret_cast<const float4*>(ctx + (size_t)row * DIM);
#pragma unroll
        for (int q = 0; q < 4; q++) {
            float4 a = wp[q];
            x[4 * q + 0] = a.x; x[4 * q + 1] = a.y; x[4 * q + 2] = a.z; x[4 * q + 3] = a.w;
            float4 b = cp[q];
            c[4 * q + 0] = b.x; c[4 * q + 1] = b.y; c[4 * q + 2] = b.z; c[4 * q + 3] = b.w;
        }
    }

    // layerI1: 16 -> 48
    float t0[DIM1];
#pragma unroll
    for (int j = 0; j < DIM1; j++) t0[j] = __ldg(&bI1[j]) + dotN<16>(WI1 + j * 16, x);

    // layerA1: 48 -> 16
    float op[DIM];
#pragma unroll
    for (int i = 0; i < DIM; i++) op[i] = __ldg(&bA1[i]) + dotN<48>(WA1 + i * 48, t0);

    // M1 over [out(48), ctx(16), op(16)]
    float h[DIM1];
#pragma unroll
    for (int j = 0; j < DIM1; j++) {
        const float* w = &sWM1[j * 80];
        h[j] = __ldg(&bM1[j]) + dotN<48>(w, t0) + dotN<16>(w + 48, c) + dotN<16>(w + 64, op);
    }
    ln_silu(h, lng, lnb);

    // scores + top-3 (strict >, first occurrence -> matches jax top_k tie-break)
    const float* trow = th + (size_t)row * TTH * DIM;
    float sc[TTH];
#pragma unroll
    for (int t = 0; t < TTH; t++) sc[t] = dotN<16>(trow + t * DIM, op);

    int best[3];
#pragma unroll
    for (int s = 0; s < 3; s++) {
        float bv = -1e30f;
        int bi = 0;
#pragma unroll
        for (int t = 0; t < TTH; t++) {
            if (sc[t] > bv) { bv = sc[t]; bi = t; }
        }
        best[s] = bi;
#pragma unroll
        for (int t = 0; t < TTH; t++)
            if (t == bi) sc[t] = -1e30f;
    }

    float tp[48];
#pragma unroll
    for (int s = 0; s < 3; s++) {
        const float4* tr = reinterpret_cast<const float4*>(trow + best[s] * DIM);
#pragma unroll
        for (int q = 0; q < 4; q++) {
            float4 a = tr[q];
            tp[s * 16 + 4 * q + 0] = a.x;
            tp[s * 16 + 4 * q + 1] = a.y;
            tp[s * 16 + 4 * q + 2] = a.z;
            tp[s * 16 + 4 * q + 3] = a.w;
        }
    }

    // M2 over [h(48), top_flat(48), ctx(16)]
    float h2[DIM1];
#pragma unroll
    for (int j = 0; j < DIM1; j++) {
        const float* w = &sWM2[j * 112];
        h2[j] = __ldg(&bM2[j]) + dotN<48>(w, h) + dotN<48>(w + 48, tp) + dotN<16>(w + 96, c);
    }
    ln_silu(h2, lng, lnb);

    // M3: 48 -> 48
    float h3[DIM1];
#pragma unroll
    for (int j = 0; j < DIM1; j++)
        h3[j] = __ldg(&bM3[j]) + dotN<48>(&sWM3[j * DIM1], h2);
    ln_silu(h3, lng, lnb);

    // O1: 48 -> 16, write to g_o
    float o[DIM];
#pragma unroll
    for (int i = 0; i < DIM; i++) o[i] = __ldg(&bO1[i]) + dotN<48>(WO1 + i * 48, h3);

    float4* od = reinterpret_cast<float4*>(g_o + (size_t)row * DIM);
#pragma unroll
    for (int q = 0; q < 4; q++)
        od[q] = make_float4(o[4 * q + 0], o[4 * q + 1], o[4 * q + 2], o[4 * q + 3]);
}

// ---------------------------------------------------------------------------
// Kernel B: logits = o @ E^T, packed-f32x2 FMA, HBM-write bound.
// Block = 256 threads, 4 vocab cols/thread (1024 vocab/block), 128 rows/block.
// ---------------------------------------------------------------------------
__device__ __forceinline__ unsigned long long ffma2(unsigned long long a,
                                                    unsigned long long b,
                                                    unsigned long long c) {
    unsigned long long d;
    asm("fma.rn.f32x2 %0, %1, %2, %3;" : "=l"(d) : "l"(a), "l"(b), "l"(c));
    return d;
}
__device__ __forceinline__ unsigned long long pack2(float x, float y) {
    unsigned long long r;
    asm("mov.b64 %0, {%1, %2};" : "=l"(r) : "f"(x), "f"(y));
    return r;
}
__device__ __forceinline__ float2 unpack2(unsigned long long v) {
    float2 r;
    asm("mov.b64 {%0, %1}, %2;" : "=f"(r.x), "=f"(r.y) : "l"(v));
    return r;
}

#define BT 128  // rows per block

__global__ void __launch_bounds__(256) logits_kernel(
    const float* __restrict__ E, float* __restrict__ out) {
    __shared__ __align__(16) unsigned long long shO[BT * DIM];  // {o,o} duplicated, 16 KB

    int vb = blockIdx.x * 1024 + threadIdx.x * 4;
    int rb = blockIdx.y * BT;
    bool vok = vb < VOCAB;           // VOCAB % 4 == 0, so all-4 valid or none
    int vsafe = vok ? vb : 0;

    // Embed rows v..v+3 into registers, pre-paired for f32x2.
    unsigned long long ew01[16], ew23[16];
    {
        const float4* e0 = reinterpret_cast<const float4*>(E + (size_t)vsafe * DIM);
#pragma unroll
        for (int q = 0; q < 4; q++) {
            float4 a = e0[q];       // row v
            float4 b = e0[q + 4];   // row v+1
            float4 c4 = e0[q + 8];  // row v+2
            float4 d = e0[q + 12];  // row v+3
            ew01[4 * q + 0] = pack2(a.x, b.x);
            ew01[4 * q + 1] = pack2(a.y, b.y);
            ew01[4 * q + 2] = pack2(a.z, b.z);
            ew01[4 * q + 3] = pack2(a.w, b.w);
            ew23[4 * q + 0] = pack2(c4.x, d.x);
            ew23[4 * q + 1] = pack2(c4.y, d.y);
            ew23[4 * q + 2] = pack2(c4.z, d.z);
            ew23[4 * q + 3] = pack2(c4.w, d.w);
        }
    }

    // Stage 128 o-rows, duplicated into both f32x2 lanes.
    for (int i = threadIdx.x; i < BT * DIM; i += 256) {
        float v = g_o[(size_t)rb * DIM + i];
        shO[i] = pack2(v, v);
    }
    __syncthreads();

#pragma unroll 1
    for (int r = 0; r < BT; r++) {
        const ulonglong2* od = reinterpret_cast<const ulonglong2*>(&shO[r * DIM]);
        unsigned long long a01 = 0ull, a23 = 0ull;  // bits of {0.f, 0.f}
#pragma unroll
        for (int kk = 0; kk < 8; kk++) {
            ulonglong2 o2 = od[kk];
            a01 = ffma2(ew01[2 * kk + 0], o2.x, a01);
            a23 = ffma2(ew23[2 * kk + 0], o2.x, a23);
            a01 = ffma2(ew01[2 * kk + 1], o2.y, a01);
            a23 = ffma2(ew23[2 * kk + 1], o2.y, a23);
        }
        if (vok) {
            float2 r01 = unpack2(a01);
            float2 r23 = unpack2(a23);
            *reinterpret_cast<float4*>(out + (size_t)(rb + r) * VOCAB + vb) =
                make_float4(r01.x, r01.y, r23.x, r23.y);
        }
    }
}

// ---------------------------------------------------------------------------
extern "C" void kernel_launch(void* const* d_in, const int* in_sizes, int n_in,
                              void* d_out, int out_size) {
    const float* we  = (const float*)d_in[0];
    const float* ctx = (const float*)d_in[1];
    const float* th  = (const float*)d_in[2];
    const float* WI1 = (const float*)d_in[3];
    const float* bI1 = (const float*)d_in[4];
    const float* WA1 = (const float*)d_in[5];
    const float* bA1 = (const float*)d_in[6];
    const float* WM1 = (const float*)d_in[7];
    const float* bM1 = (const float*)d_in[8];
    const float* WM2 = (const float*)d_in[9];
    const float* bM2 = (const float*)d_in[10];
    const float* WM3 = (const float*)d_in[11];
    const float* bM3 = (const float*)d_in[12];
    const float* lng = (const float*)d_in[13];
    const float* lnb = (const float*)d_in[14];
    const float* WO1 = (const float*)d_in[15];
    const float* bO1 = (const float*)d_in[16];
    const float* E   = (const float*)d_in[17];
    float* out = (float*)d_out;

    rowmlp_kernel<<<BATCH / 64, 64>>>(we, ctx, th, WI1, bI1, WA1, bA1, WM1, bM1,
                                      WM2, bM2, WM3, bM3, lng, lnb, WO1, bO1);
    logits_kernel<<<dim3((VOCAB + 1023) / 1024, BATCH / BT), 256>>>(E, out);
}

// round 6
// speedup vs baseline: 1.1560x; 1.1560x over previous
#include <cuda_runtime.h>
#include <math.h>

#define BATCH 8192
#define DIM 16
#define DIM1 48
#define VOCAB 32000
#define TTH 20
#define FULLM 0xffffffffu

// Intermediate o = [BATCH, 16] between the two kernels (static scratch, no allocs).
__device__ float g_o[BATCH * DIM];

// ---------------------------------------------------------------------------
// Kernel A: cooperative 16-lanes-per-row MLP pipeline.
// Distribution: 48-vectors -> lane owns {lane, lane+16, lane+32};
//               16-vectors -> lane owns {lane}.
// Weight rows padded to stride S with S mod 32 == 20 -> conflict-free LDS.128.
// ---------------------------------------------------------------------------

#define S_M1 84   // 80 -> 84
#define S_M2 116  // 112 -> 116
#define S_M3 52   // 48 -> 52

// Accumulate 3 outputs (rows lane+16r of W, stride S) over one 16-element
// distributed input segment v (held one elem per lane), columns [kbase, kbase+16).
__device__ __forceinline__ void acc48(float acc[3], float v,
                                      const float* __restrict__ W, int S,
                                      int lane, int kbase) {
#pragma unroll
    for (int kk = 0; kk < 16; kk += 4) {
        float b0 = __shfl_sync(FULLM, v, kk + 0, 16);
        float b1 = __shfl_sync(FULLM, v, kk + 1, 16);
        float b2 = __shfl_sync(FULLM, v, kk + 2, 16);
        float b3 = __shfl_sync(FULLM, v, kk + 3, 16);
#pragma unroll
        for (int r = 0; r < 3; r++) {
            float4 w = *reinterpret_cast<const float4*>(
                &W[(lane + 16 * r) * S + kbase + kk]);
            acc[r] += w.x * b0 + w.y * b1 + w.z * b2 + w.w * b3;
        }
    }
}

// Accumulate 1 output (row `lane` of W, stride S) over one 16-element segment.
__device__ __forceinline__ void acc16(float& acc, float v,
                                      const float* __restrict__ W, int S,
                                      int lane, int kbase) {
#pragma unroll
    for (int kk = 0; kk < 16; kk += 4) {
        float b0 = __shfl_sync(FULLM, v, kk + 0, 16);
        float b1 = __shfl_sync(FULLM, v, kk + 1, 16);
        float b2 = __shfl_sync(FULLM, v, kk + 2, 16);
        float b3 = __shfl_sync(FULLM, v, kk + 3, 16);
        float4 w = *reinterpret_cast<const float4*>(&W[lane * S + kbase + kk]);
        acc += w.x * b0 + w.y * b1 + w.z * b2 + w.w * b3;
    }
}

__device__ __forceinline__ void ln_silu3(float v[3],
                                         const float* __restrict__ g,
                                         const float* __restrict__ b,
                                         int lane) {
    float s = v[0] + v[1] + v[2];
    float q = v[0] * v[0] + v[1] * v[1] + v[2] * v[2];
#pragma unroll
    for (int off = 8; off >= 1; off >>= 1) {
        s += __shfl_xor_sync(FULLM, s, off, 16);
        q += __shfl_xor_sync(FULLM, q, off, 16);
    }
    float mu = s * (1.f / DIM1);
    float var = q * (1.f / DIM1) - mu * mu;
    float inv = rsqrtf(var + 1e-5f);
#pragma unroll
    for (int r = 0; r < 3; r++) {
        float t = (v[r] - mu) * inv * __ldg(&g[lane + 16 * r]) + __ldg(&b[lane + 16 * r]);
        v[r] = t / (1.f + expf(-t));
    }
}

__global__ void __launch_bounds__(512) rowmlp_kernel(
    const float* __restrict__ we, const float* __restrict__ ctx,
    const float* __restrict__ th,
    const float* __restrict__ WI1, const float* __restrict__ bI1,
    const float* __restrict__ WA1, const float* __restrict__ bA1,
    const float* __restrict__ WM1, const float* __restrict__ bM1,
    const float* __restrict__ WM2, const float* __restrict__ bM2,
    const float* __restrict__ WM3, const float* __restrict__ bM3,
    const float* __restrict__ lng, const float* __restrict__ lnb,
    const float* __restrict__ WO1, const float* __restrict__ bO1) {
    // Only the three big M weights go to shared (48384 B, fits static 48KB).
    __shared__ __align__(16) float sWM1[DIM1 * S_M1];
    __shared__ __align__(16) float sWM2[DIM1 * S_M2];
    __shared__ __align__(16) float sWM3[DIM1 * S_M3];

    int tid = threadIdx.x;
    for (int i = tid; i < DIM1 * 80; i += 512) sWM1[(i / 80) * S_M1 + (i % 80)] = WM1[i];
    for (int i = tid; i < DIM1 * 112; i += 512) sWM2[(i / 112) * S_M2 + (i % 112)] = WM2[i];
    for (int i = tid; i < DIM1 * 48; i += 512) sWM3[(i / 48) * S_M3 + (i % 48)] = WM3[i];
    __syncthreads();

    int lane = tid & 15;
    int row = blockIdx.x * 32 + (tid >> 4);

    float x = we[(size_t)row * DIM + lane];
    float c = ctx[(size_t)row * DIM + lane];

    // layerI1: 16 -> 48 (weights from global, L1-resident; stride 16, j = lane+16r)
    float t0[3];
#pragma unroll
    for (int r = 0; r < 3; r++) t0[r] = __ldg(&bI1[lane + 16 * r]);
    {
#pragma unroll
        for (int kk = 0; kk < 16; kk += 4) {
            float b0 = __shfl_sync(FULLM, x, kk + 0, 16);
            float b1 = __shfl_sync(FULLM, x, kk + 1, 16);
            float b2 = __shfl_sync(FULLM, x, kk + 2, 16);
            float b3 = __shfl_sync(FULLM, x, kk + 3, 16);
#pragma unroll
            for (int r = 0; r < 3; r++) {
                float4 w = *reinterpret_cast<const float4*>(
                    &WI1[(lane + 16 * r) * 16 + kk]);
                t0[r] += w.x * b0 + w.y * b1 + w.z * b2 + w.w * b3;
            }
        }
    }

    // layerA1: 48 -> 16 (global weights, stride 48)
    float op = __ldg(&bA1[lane]);
    acc16(op, t0[0], WA1, 48, lane, 0);
    acc16(op, t0[1], WA1, 48, lane, 16);
    acc16(op, t0[2], WA1, 48, lane, 32);

    // M1 over [t0(48), c(16), op(16)]
    float h[3];
#pragma unroll
    for (int r = 0; r < 3; r++) h[r] = __ldg(&bM1[lane + 16 * r]);
    acc48(h, t0[0], sWM1, S_M1, lane, 0);
    acc48(h, t0[1], sWM1, S_M1, lane, 16);
    acc48(h, t0[2], sWM1, S_M1, lane, 32);
    acc48(h, c, sWM1, S_M1, lane, 48);
    acc48(h, op, sWM1, S_M1, lane, 64);
    ln_silu3(h, lng, lnb, lane);

    // scores + top-3 (strict >, first occurrence == jax tie-break)
    float opAll[16];
#pragma unroll
    for (int k = 0; k < 16; k++) opAll[k] = __shfl_sync(FULLM, op, k, 16);

    const float* trow = th + (size_t)row * TTH * DIM;
    float s0 = 0.f;
    {
        const float4* tr = reinterpret_cast<const float4*>(trow + lane * DIM);
#pragma unroll
        for (int q = 0; q < 4; q++) {
            float4 a = tr[q];
            s0 += a.x * opAll[4 * q + 0] + a.y * opAll[4 * q + 1] +
                  a.z * opAll[4 * q + 2] + a.w * opAll[4 * q + 3];
        }
    }
    float s1 = -1e30f;
    if (lane < 4) {
        const float4* tr = reinterpret_cast<const float4*>(trow + (16 + lane) * DIM);
        float acc = 0.f;
#pragma unroll
        for (int q = 0; q < 4; q++) {
            float4 a = tr[q];
            acc += a.x * opAll[4 * q + 0] + a.y * opAll[4 * q + 1] +
                   a.z * opAll[4 * q + 2] + a.w * opAll[4 * q + 3];
        }
        s1 = acc;
    }
    float sc[TTH];
#pragma unroll
    for (int t = 0; t < 16; t++) sc[t] = __shfl_sync(FULLM, s0, t, 16);
#pragma unroll
    for (int t = 16; t < TTH; t++) sc[t] = __shfl_sync(FULLM, s1, t - 16, 16);

    int best[3];
#pragma unroll
    for (int s3 = 0; s3 < 3; s3++) {
        float bv = -1e30f;
        int bi = 0;
#pragma unroll
        for (int t = 0; t < TTH; t++) {
            if (sc[t] > bv) { bv = sc[t]; bi = t; }
        }
        best[s3] = bi;
#pragma unroll
        for (int t = 0; t < TTH; t++)
            if (t == bi) sc[t] = -1e30f;
    }

    float tp[3];
#pragma unroll
    for (int s3 = 0; s3 < 3; s3++) tp[s3] = __ldg(&trow[best[s3] * DIM + lane]);

    // M2 over [h(48), top_flat(48), c(16)]
    float h2[3];
#pragma unroll
    for (int r = 0; r < 3; r++) h2[r] = __ldg(&bM2[lane + 16 * r]);
    acc48(h2, h[0], sWM2, S_M2, lane, 0);
    acc48(h2, h[1], sWM2, S_M2, lane, 16);
    acc48(h2, h[2], sWM2, S_M2, lane, 32);
    acc48(h2, tp[0], sWM2, S_M2, lane, 48);
    acc48(h2, tp[1], sWM2, S_M2, lane, 64);
    acc48(h2, tp[2], sWM2, S_M2, lane, 80);
    acc48(h2, c, sWM2, S_M2, lane, 96);
    ln_silu3(h2, lng, lnb, lane);

    // M3: 48 -> 48
    float h3[3];
#pragma unroll
    for (int r = 0; r < 3; r++) h3[r] = __ldg(&bM3[lane + 16 * r]);
    acc48(h3, h2[0], sWM3, S_M3, lane, 0);
    acc48(h3, h2[1], sWM3, S_M3, lane, 16);
    acc48(h3, h2[2], sWM3, S_M3, lane, 32);
    ln_silu3(h3, lng, lnb, lane);

    // O1: 48 -> 16 (global weights, stride 48)
    float o = __ldg(&bO1[lane]);
    acc16(o, h3[0], WO1, 48, lane, 0);
    acc16(o, h3[1], WO1, 48, lane, 16);
    acc16(o, h3[2], WO1, 48, lane, 32);

    g_o[(size_t)row * DIM + lane] = o;
}

// ---------------------------------------------------------------------------
// Kernel B: logits = o @ E^T via packed f32x2 FMA (FFMA2 rt~1/SMSP).
// 2 vocab cols/thread (32 E-pair regs), 2 independent 8-deep accum chains,
// 256 thr/block, 512 cols/block, 128 rows/block. shO loads are all-lane
// broadcast (free on the crossbar).
// ---------------------------------------------------------------------------
__device__ __forceinline__ unsigned long long ffma2(unsigned long long a,
                                                    unsigned long long b,
                                                    unsigned long long c) {
    unsigned long long d;
    asm("fma.rn.f32x2 %0, %1, %2, %3;" : "=l"(d) : "l"(a), "l"(b), "l"(c));
    return d;
}
__device__ __forceinline__ unsigned long long addf2(unsigned long long a,
                                                    unsigned long long b) {
    unsigned long long d;
    asm("add.rn.f32x2 %0, %1, %2;" : "=l"(d) : "l"(a), "l"(b));
    return d;
}
__device__ __forceinline__ unsigned long long pack2(float x, float y) {
    unsigned long long r;
    asm("mov.b64 %0, {%1, %2};" : "=l"(r) : "f"(x), "f"(y));
    return r;
}
__device__ __forceinline__ float2 unpack2(unsigned long long v) {
    float2 r;
    asm("mov.b64 {%0, %1}, %2;" : "=f"(r.x), "=f"(r.y) : "l"(v));
    return r;
}

#define BT 128  // rows per block

__global__ void __launch_bounds__(256) logits_kernel(
    const float* __restrict__ E, float* __restrict__ out) {
    __shared__ __align__(16) unsigned long long shO[BT * DIM];  // {o,o} pairs

    int vb = blockIdx.x * 512 + threadIdx.x * 2;
    int rb = blockIdx.y * BT;
    bool vok = vb < VOCAB;  // VOCAB even, vb even -> pair fully valid or not
    int vsafe = vok ? vb : 0;

    // Embed rows v, v+1 pre-paired for f32x2: ew[k] = {E[v][k], E[v+1][k]}
    unsigned long long ew[16];
    {
        const float4* e0 = reinterpret_cast<const float4*>(E + (size_t)vsafe * DIM);
#pragma unroll
        for (int q = 0; q < 4; q++) {
            float4 a = e0[q];      // row v
            float4 b = e0[q + 4];  // row v+1
            ew[4 * q + 0] = pack2(a.x, b.x);
            ew[4 * q + 1] = pack2(a.y, b.y);
            ew[4 * q + 2] = pack2(a.z, b.z);
            ew[4 * q + 3] = pack2(a.w, b.w);
        }
    }

    // Stage 128 o-rows, duplicated into both f32x2 lanes.
    for (int i = threadIdx.x; i < BT * DIM; i += 256) {
        float v = g_o[(size_t)rb * DIM + i];
        shO[i] = pack2(v, v);
    }
    __syncthreads();

#pragma unroll 2
    for (int r = 0; r < BT; r++) {
        const ulonglong2* od = reinterpret_cast<const ulonglong2*>(&shO[r * DIM]);
        unsigned long long a0 = 0ull, a1 = 0ull;  // two independent chains
#pragma unroll
        for (int kk = 0; kk < 8; kk++) {
            ulonglong2 o2 = od[kk];
            a0 = ffma2(ew[2 * kk + 0], o2.x, a0);
            a1 = ffma2(ew[2 * kk + 1], o2.y, a1);
        }
        if (vok) {
            float2 res = unpack2(addf2(a0, a1));
            *reinterpret_cast<float2*>(out + (size_t)(rb + r) * VOCAB + vb) = res;
        }
    }
}

// ---------------------------------------------------------------------------
extern "C" void kernel_launch(void* const* d_in, const int* in_sizes, int n_in,
                              void* d_out, int out_size) {
    const float* we  = (const float*)d_in[0];
    const float* ctx = (const float*)d_in[1];
    const float* th  = (const float*)d_in[2];
    const float* WI1 = (const float*)d_in[3];
    const float* bI1 = (const float*)d_in[4];
    const float* WA1 = (const float*)d_in[5];
    const float* bA1 = (const float*)d_in[6];
    const float* WM1 = (const float*)d_in[7];
    const float* bM1 = (const float*)d_in[8];
    const float* WM2 = (const float*)d_in[9];
    const float* bM2 = (const float*)d_in[10];
    const float* WM3 = (const float*)d_in[11];
    const float* bM3 = (const float*)d_in[12];
    const float* lng = (const float*)d_in[13];
    const float* lnb = (const float*)d_in[14];
    const float* WO1 = (const float*)d_in[15];
    const float* bO1 = (const float*)d_in[16];
    const float* E   = (const float*)d_in[17];
    float* out = (float*)d_out;

    // 32 rows/block * 16 lanes = 512 threads; 8192/32 = 256 blocks.
    rowmlp_kernel<<<256, 512>>>(we, ctx, th, WI1, bI1, WA1, bA1, WM1, bM1,
                                WM2, bM2, WM3, bM3, lng, lnb, WO1, bO1);
    // 512 cols/block -> ceil(32000/512)=63 x-blocks; 8192/128 = 64 y-blocks.
    logits_kernel<<<dim3(63, BATCH / BT), 256>>>(E, out);
}